// round 4
// baseline (speedup 1.0000x reference)
#include <cuda_runtime.h>
#include <math_constants.h>

#define IN_DIM   256
#define CODE_LEN 128
#define MEM_LEN  65536

#define GRID_S   1024      // stats: 262144 threads -> exactly 16 float4/thread
#define GRID_D   1024      // dist : 8192 warps    -> exactly 8 rows/warp
#define NT       256

// Output layout (flattened tuple, all f32):
#define OUT_MEM_OFF 1LL
#define OUT_MD_OFF  (1LL + (long long)MEM_LEN * CODE_LEN)
#define OUT_IDX_OFF (OUT_MD_OFF + (long long)MEM_LEN * IN_DIM)

// Scratch (device globals; statically armed, re-armed by the final block)
__device__ float               g_colsum[IN_DIM];                  // zero-init
__device__ float               g_colsq[IN_DIM];                   // zero-init
__device__ __align__(16) float g_enc[CODE_LEN];
__device__ int                 g_minbits = 0x7f800000;            // +inf
__device__ unsigned long long  g_argmin  = 0xFFFFFFFFFFFFFFFFULL;
__device__ unsigned            g_ticket  = 0;

__device__ __forceinline__ void st4(float* __restrict__ o, float4 v) {
    o[0] = v.x; o[1] = v.y; o[2] = v.z; o[3] = v.w;
}

// ---------------------------------------------------------------------------
// K1: mem_data [65536,256] — copy + column sum/sumsq, batched MLP=4.
//     4*nthr % 256 == 0 -> each thread's 4 columns fixed: (4*gtid)&255.
//     Plus mem_idx copy + packed argmin (first 256 blocks).
// ---------------------------------------------------------------------------
__global__ void __launch_bounds__(NT)
k_stats(const float4* __restrict__ md4, float* __restrict__ out_md,
        const int* __restrict__ idx, float* __restrict__ out_idx) {
    const int tid  = threadIdx.x;
    const int gtid = blockIdx.x * NT + tid;
    const int nthr = GRID_S * NT;                    // 262144

    float s0 = 0, s1 = 0, s2 = 0, s3 = 0;
    float q0 = 0, q1 = 0, q2 = 0, q3 = 0;
    long long i = gtid;
    #pragma unroll
    for (int o = 0; o < 4; o++) {                    // 4 batches of 4 -> 16 total
        float4 a = md4[i];
        float4 b = md4[i + (long long)nthr];
        float4 c = md4[i + 2LL * nthr];
        float4 d = md4[i + 3LL * nthr];
        st4(out_md + 4 * i,                 a);
        st4(out_md + 4 * (i + (long long)nthr), b);
        st4(out_md + 4 * (i + 2LL * nthr),  c);
        st4(out_md + 4 * (i + 3LL * nthr),  d);
        s0 += a.x + b.x + c.x + d.x;
        s1 += a.y + b.y + c.y + d.y;
        s2 += a.z + b.z + c.z + d.z;
        s3 += a.w + b.w + c.w + d.w;
        q0 += a.x * a.x + b.x * b.x + c.x * c.x + d.x * d.x;
        q1 += a.y * a.y + b.y * b.y + c.y * c.y + d.y * d.y;
        q2 += a.z * a.z + b.z * b.z + c.z * c.z + d.z * d.z;
        q3 += a.w * a.w + b.w * b.w + c.w * c.w + d.w * d.w;
        i += 4LL * nthr;
    }

    __shared__ float sh_s[4][IN_DIM];
    __shared__ float sh_q[4][IN_DIM];
    int col = (4 * tid) & 255, grp = tid >> 6;
    sh_s[grp][col] = s0; sh_s[grp][col + 1] = s1; sh_s[grp][col + 2] = s2; sh_s[grp][col + 3] = s3;
    sh_q[grp][col] = q0; sh_q[grp][col + 1] = q1; sh_q[grp][col + 2] = q2; sh_q[grp][col + 3] = q3;
    __syncthreads();
    atomicAdd(&g_colsum[tid], sh_s[0][tid] + sh_s[1][tid] + sh_s[2][tid] + sh_s[3][tid]);
    atomicAdd(&g_colsq[tid],  sh_q[0][tid] + sh_q[1][tid] + sh_q[2][tid] + sh_q[3][tid]);

    if (gtid < MEM_LEN) {
        int v = idx[gtid];
        out_idx[gtid] = (float)v;
        unsigned long long key =
            ((unsigned long long)(unsigned)(v ^ 0x80000000) << 32) | (unsigned long long)gtid;
        #pragma unroll
        for (int off = 16; off; off >>= 1) {
            unsigned long long o = __shfl_xor_sync(0xFFFFFFFFu, key, off);
            key = (o < key) ? o : key;
        }
        if ((tid & 31) == 0) atomicMin(&g_argmin, key);
    }
}

// ---------------------------------------------------------------------------
// K2: enc = ((x-mean)/std) @ W.T + b — one output row per block.
// ---------------------------------------------------------------------------
__global__ void __launch_bounds__(NT)
k_enc(const float* __restrict__ x, const float* __restrict__ W,
      const float* __restrict__ b) {
    int row = blockIdx.x, t = threadIdx.x;
    float mean = g_colsum[t] * (1.0f / (float)MEM_LEN);
    float var  = (g_colsq[t] - (float)MEM_LEN * mean * mean) * (1.0f / (float)(MEM_LEN - 1));
    float sd   = sqrtf(fmaxf(var, 0.0f));
    float nv   = (sd == 0.0f) ? 0.0f : (x[t] - mean) / sd;
    float p    = nv * W[(long long)row * IN_DIM + t];
    #pragma unroll
    for (int off = 16; off; off >>= 1) p += __shfl_xor_sync(0xFFFFFFFFu, p, off);
    __shared__ float red[8];
    if ((t & 31) == 0) red[t >> 5] = p;
    __syncthreads();
    if (t == 0) {
        float a = b[row];
        #pragma unroll
        for (int i = 0; i < 8; i++) a += red[i];
        g_enc[row] = a;
    }
}

// ---------------------------------------------------------------------------
// K3: memory [65536,128] — copy + L1 distance (warp-per-row, 2 batches of 4
//     rows -> MLP 4), running min, global atomicMin, then LAST BLOCK writes
//     loss + conditional scatter and re-arms all accumulators.
// ---------------------------------------------------------------------------
__global__ void __launch_bounds__(NT)
k_dist(const float4* __restrict__ mem4, float* __restrict__ out_mem,
       const float* __restrict__ x, const int* __restrict__ count,
       float* __restrict__ out) {
    const int tid   = threadIdx.x;
    const int lane  = tid & 31;
    const int warp  = (blockIdx.x * NT + tid) >> 5;
    const int nwarp = (GRID_D * NT) >> 5;           // 8192

    float4 e = reinterpret_cast<const float4*>(g_enc)[lane];
    float best = CUDART_INF_F;

    #pragma unroll
    for (int k = 0; k < 8; k += 4) {
        int r0 = warp + (k + 0) * nwarp;
        int r1 = warp + (k + 1) * nwarp;
        int r2 = warp + (k + 2) * nwarp;
        int r3 = warp + (k + 3) * nwarp;
        float4 a = mem4[(long long)r0 * 32 + lane];
        float4 b = mem4[(long long)r1 * 32 + lane];
        float4 c = mem4[(long long)r2 * 32 + lane];
        float4 d = mem4[(long long)r3 * 32 + lane];
        st4(out_mem + (long long)r0 * 128 + lane * 4, a);
        st4(out_mem + (long long)r1 * 128 + lane * 4, b);
        st4(out_mem + (long long)r2 * 128 + lane * 4, c);
        st4(out_mem + (long long)r3 * 128 + lane * 4, d);
        float d0 = fabsf(a.x - e.x) + fabsf(a.y - e.y) + fabsf(a.z - e.z) + fabsf(a.w - e.w);
        float d1 = fabsf(b.x - e.x) + fabsf(b.y - e.y) + fabsf(b.z - e.z) + fabsf(b.w - e.w);
        float d2 = fabsf(c.x - e.x) + fabsf(c.y - e.y) + fabsf(c.z - e.z) + fabsf(c.w - e.w);
        float d3 = fabsf(d.x - e.x) + fabsf(d.y - e.y) + fabsf(d.z - e.z) + fabsf(d.w - e.w);
        #pragma unroll
        for (int off = 16; off; off >>= 1) {
            d0 += __shfl_xor_sync(0xFFFFFFFFu, d0, off);
            d1 += __shfl_xor_sync(0xFFFFFFFFu, d1, off);
            d2 += __shfl_xor_sync(0xFFFFFFFFu, d2, off);
            d3 += __shfl_xor_sync(0xFFFFFFFFu, d3, off);
        }
        best = fminf(best, fminf(fminf(d0, d1), fminf(d2, d3)));
    }
    if (lane == 0) atomicMin(&g_minbits, __float_as_int(best));

    // --- last-block final ---
    __threadfence();
    __syncthreads();
    __shared__ int s_last;
    if (tid == 0) s_last = (atomicAdd(&g_ticket, 1) == GRID_D - 1) ? 1 : 0;
    __syncthreads();
    if (s_last) {
        float loss = __int_as_float(atomicAdd(&g_minbits, 0));
        unsigned long long am = atomicAdd(&g_argmin, 0ULL);
        long long pos = (long long)(unsigned)(am & 0xFFFFFFFFULL);
        if (tid == 0) out[0] = loss;
        if (loss <= 1.0f) {
            if (tid < CODE_LEN) out[OUT_MEM_OFF + pos * CODE_LEN + tid] = g_enc[tid];
            out[OUT_MD_OFF + pos * IN_DIM + tid] = x[tid];
            if (tid == 0) out[OUT_IDX_OFF + pos] = (float)count[0];
        }
        __syncthreads();                 // done reading accumulators
        g_colsum[tid] = 0.0f;            // re-arm for next graph replay
        g_colsq[tid]  = 0.0f;
        if (tid == 0) {
            g_minbits = 0x7f800000;
            g_argmin  = 0xFFFFFFFFFFFFFFFFULL;
            g_ticket  = 0;
        }
    }
}

// ---------------------------------------------------------------------------
extern "C" void kernel_launch(void* const* d_in, const int* in_sizes, int n_in,
                              void* d_out, int out_size) {
    const float* x        = (const float*)d_in[0];
    const float* memory   = (const float*)d_in[1];
    const float* mem_data = (const float*)d_in[2];
    const int*   mem_idx  = (const int*)d_in[3];
    const float* W        = (const float*)d_in[4];
    const float* b        = (const float*)d_in[5];
    const int*   count    = (const int*)d_in[6];
    float* out = (float*)d_out;

    k_stats<<<GRID_S, NT>>>((const float4*)mem_data, out + OUT_MD_OFF,
                            mem_idx, out + OUT_IDX_OFF);
    k_enc  <<<CODE_LEN, NT>>>(x, W, b);
    k_dist <<<GRID_D, NT>>>((const float4*)memory, out + OUT_MEM_OFF,
                            x, count, out);
}

// round 5
// speedup vs baseline: 1.1579x; 1.1579x over previous
#include <cuda_runtime.h>
#include <math_constants.h>

#define IN_DIM   256
#define CODE_LEN 128
#define MEM_LEN  65536
#define NT       256
#define GRID_S   888          // 148 * 6
#define GRID_D   888

#define N_MD  ((long long)MEM_LEN * IN_DIM)      // 16777216 floats
#define N_MEM ((long long)MEM_LEN * CODE_LEN)    //  8388608 floats
// Aligned-slot counts: slots start at out_base+3, 4 floats each
#define S_MD  ((N_MD  - 7) / 4 + 1)              // 4194303
#define S_MEM ((N_MEM - 7) / 4 + 1)              // 2097151

// Output layout (flattened tuple, all f32):
#define OUT_MEM_OFF 1LL
#define OUT_MD_OFF  (1LL + N_MEM)
#define OUT_IDX_OFF (OUT_MD_OFF + N_MD)

// Scratch (device globals; statically armed, re-armed by the final block)
__device__ float               g_colsum[IN_DIM];                  // zero-init
__device__ float               g_colsq[IN_DIM];                   // zero-init
__device__ __align__(16) float g_enc[CODE_LEN];
__device__ int                 g_minbits = 0x7f800000;            // +inf
__device__ unsigned long long  g_argmin  = 0xFFFFFFFFFFFFFFFFULL;
__device__ unsigned            g_ticket  = 0;

// ---------------------------------------------------------------------------
// K1: mem_data [65536,256] — realigned copy (STG.128) + column sum/sumsq.
//     Slot k (16B-aligned in the output) = {md4[k].w, md4[k+1].xyz}.
//     Thread loads md4[k+1]; missing .w comes via shfl_up (lane0: scalar).
//     Fixed columns per thread: elements 4(k+1)+c, k ≡ tid (mod 64).
//     Plus mem_idx copy + packed argmin.
// ---------------------------------------------------------------------------
__global__ void __launch_bounds__(NT)
k_stats(const float* __restrict__ md_f, float* __restrict__ out_md,
        const int* __restrict__ idx, float* __restrict__ out_idx) {
    const float4* md4  = (const float4*)md_f;
    float4*       out4 = (float4*)(out_md + 3);        // 16B-aligned
    const int tid  = threadIdx.x;
    const int lane = tid & 31;
    const long long nslot = (long long)GRID_S * NT;

    float s0 = 0, s1 = 0, s2 = 0, s3 = 0;
    float q0 = 0, q1 = 0, q2 = 0, q3 = 0;
    for (long long wb = (long long)blockIdx.x * NT + (tid & ~31); wb < S_MD; wb += nslot) {
        long long k = wb + lane;
        bool ok = k < S_MD;
        float4 v = ok ? md4[k + 1] : make_float4(0.f, 0.f, 0.f, 0.f);
        float pw = __shfl_up_sync(0xFFFFFFFFu, v.w, 1);
        if (lane == 0) pw = md_f[4 * wb + 3];
        if (ok) out4[k] = make_float4(pw, v.x, v.y, v.z);
        s0 += v.x; q0 += v.x * v.x;
        s1 += v.y; q1 += v.y * v.y;
        s2 += v.z; q2 += v.z * v.z;
        s3 += v.w; q3 += v.w * v.w;
    }

    // Block reduce: each 64-thread group covers all 256 cols once.
    __shared__ float sh_s[4][IN_DIM];
    __shared__ float sh_q[4][IN_DIM];
    int c0 = (4 * tid + 4) & 255, grp = tid >> 6;
    sh_s[grp][c0] = s0; sh_s[grp][c0 + 1] = s1; sh_s[grp][c0 + 2] = s2; sh_s[grp][c0 + 3] = s3;
    sh_q[grp][c0] = q0; sh_q[grp][c0 + 1] = q1; sh_q[grp][c0 + 2] = q2; sh_q[grp][c0 + 3] = q3;
    __syncthreads();
    atomicAdd(&g_colsum[tid], sh_s[0][tid] + sh_s[1][tid] + sh_s[2][tid] + sh_s[3][tid]);
    atomicAdd(&g_colsq[tid],  sh_q[0][tid] + sh_q[1][tid] + sh_q[2][tid] + sh_q[3][tid]);

    // mem_idx: copy + packed argmin (first-index tie-break)
    int gtid = blockIdx.x * NT + tid;
    if (gtid < MEM_LEN) {
        int v = idx[gtid];
        out_idx[gtid] = (float)v;
        unsigned long long key =
            ((unsigned long long)(unsigned)(v ^ 0x80000000) << 32) | (unsigned long long)gtid;
        #pragma unroll
        for (int off = 16; off; off >>= 1) {
            unsigned long long o = __shfl_xor_sync(0xFFFFFFFFu, key, off);
            key = (o < key) ? o : key;
        }
        if ((tid & 31) == 0) atomicMin(&g_argmin, key);
    }

    // Head (elements 0..2 of output) + tail (N-1) + stats for elements 0..3
    if (blockIdx.x == 0 && tid == 0) {
        out_md[0] = md_f[0]; out_md[1] = md_f[1]; out_md[2] = md_f[2];
        out_md[N_MD - 1] = md_f[N_MD - 1];
        #pragma unroll
        for (int j = 0; j < 4; j++) {
            float v = md_f[j];
            atomicAdd(&g_colsum[j], v);
            atomicAdd(&g_colsq[j],  v * v);
        }
    }
}

// ---------------------------------------------------------------------------
// K2: enc = ((x-mean)/std) @ W.T + b — one output row per block.
// ---------------------------------------------------------------------------
__global__ void __launch_bounds__(NT)
k_enc(const float* __restrict__ x, const float* __restrict__ W,
      const float* __restrict__ b) {
    int row = blockIdx.x, t = threadIdx.x;
    float mean = g_colsum[t] * (1.0f / (float)MEM_LEN);
    float var  = (g_colsq[t] - (float)MEM_LEN * mean * mean) * (1.0f / (float)(MEM_LEN - 1));
    float sd   = sqrtf(fmaxf(var, 0.0f));
    float nv   = (sd == 0.0f) ? 0.0f : (x[t] - mean) / sd;
    float p    = nv * W[(long long)row * IN_DIM + t];
    #pragma unroll
    for (int off = 16; off; off >>= 1) p += __shfl_xor_sync(0xFFFFFFFFu, p, off);
    __shared__ float red[8];
    if ((t & 31) == 0) red[t >> 5] = p;
    __syncthreads();
    if (t == 0) {
        float a = b[row];
        #pragma unroll
        for (int i = 0; i < 8; i++) a += red[i];
        g_enc[row] = a;
    }
}

// ---------------------------------------------------------------------------
// K3: memory [65536,128] — warp-per-row L1 distance + realigned copy.
//     Row r, lane l: u = mem4[r*32+l]; slot r*32+l = {u.w, next-lane u.xyz}.
//     Last block (ticket) writes loss + conditional scatter, re-arms globals.
// ---------------------------------------------------------------------------
__global__ void __launch_bounds__(NT)
k_dist(const float* __restrict__ mem_f, float* __restrict__ out_mem,
       const float* __restrict__ x, const int* __restrict__ count,
       float* __restrict__ out) {
    const float4* mem4 = (const float4*)mem_f;
    float4*       out4 = (float4*)(out_mem + 3);       // 16B-aligned
    const int tid   = threadIdx.x;
    const int lane  = tid & 31;
    const int warp  = (blockIdx.x * NT + tid) >> 5;
    const int nwarp = (GRID_D * NT) >> 5;              // 7104

    float4 e = reinterpret_cast<const float4*>(g_enc)[lane];
    float best = CUDART_INF_F;

    #pragma unroll 2
    for (int r = warp; r < MEM_LEN; r += nwarp) {
        float4 u = mem4[(long long)r * 32 + lane];
        // realigned copy
        float nx = __shfl_down_sync(0xFFFFFFFFu, u.x, 1);
        float ny = __shfl_down_sync(0xFFFFFFFFu, u.y, 1);
        float nz = __shfl_down_sync(0xFFFFFFFFu, u.z, 1);
        if (lane == 31 && r + 1 < MEM_LEN) {
            float4 t = mem4[(long long)(r + 1) * 32];
            nx = t.x; ny = t.y; nz = t.z;
        }
        long long slot = (long long)r * 32 + lane;
        if (slot < S_MEM) out4[slot] = make_float4(u.w, nx, ny, nz);
        // L1 distance
        float d = fabsf(u.x - e.x) + fabsf(u.y - e.y) + fabsf(u.z - e.z) + fabsf(u.w - e.w);
        #pragma unroll
        for (int off = 16; off; off >>= 1) d += __shfl_xor_sync(0xFFFFFFFFu, d, off);
        best = fminf(best, d);
    }
    if (lane == 0) atomicMin(&g_minbits, __float_as_int(best));

    if (blockIdx.x == 0 && tid == 0) {
        out_mem[0] = mem_f[0]; out_mem[1] = mem_f[1]; out_mem[2] = mem_f[2];
        out_mem[N_MEM - 1] = mem_f[N_MEM - 1];
    }

    // --- last-block final ---
    __threadfence();
    __syncthreads();
    __shared__ int s_last;
    if (tid == 0) s_last = (atomicAdd(&g_ticket, 1) == GRID_D - 1) ? 1 : 0;
    __syncthreads();
    if (s_last) {
        float loss = __int_as_float(atomicAdd(&g_minbits, 0));
        unsigned long long am = atomicAdd(&g_argmin, 0ULL);
        long long pos = (long long)(unsigned)(am & 0xFFFFFFFFULL);
        if (tid == 0) out[0] = loss;
        if (loss <= 1.0f) {
            if (tid < CODE_LEN) out[OUT_MEM_OFF + pos * CODE_LEN + tid] = g_enc[tid];
            out[OUT_MD_OFF + pos * IN_DIM + tid] = x[tid];
            if (tid == 0) out[OUT_IDX_OFF + pos] = (float)count[0];
        }
        __syncthreads();                 // done reading accumulators
        g_colsum[tid] = 0.0f;            // re-arm for next graph replay
        g_colsq[tid]  = 0.0f;
        if (tid == 0) {
            g_minbits = 0x7f800000;
            g_argmin  = 0xFFFFFFFFFFFFFFFFULL;
            g_ticket  = 0;
        }
    }
}

// ---------------------------------------------------------------------------
extern "C" void kernel_launch(void* const* d_in, const int* in_sizes, int n_in,
                              void* d_out, int out_size) {
    const float* x        = (const float*)d_in[0];
    const float* memory   = (const float*)d_in[1];
    const float* mem_data = (const float*)d_in[2];
    const int*   mem_idx  = (const int*)d_in[3];
    const float* W        = (const float*)d_in[4];
    const float* b        = (const float*)d_in[5];
    const int*   count    = (const int*)d_in[6];
    float* out = (float*)d_out;

    k_stats<<<GRID_S, NT>>>(mem_data, out + OUT_MD_OFF, mem_idx, out + OUT_IDX_OFF);
    k_enc  <<<CODE_LEN, NT>>>(x, W, b);
    k_dist <<<GRID_D, NT>>>(memory, out + OUT_MEM_OFF, x, count, out);
}

// round 6
// speedup vs baseline: 1.2034x; 1.0393x over previous
#include <cuda_runtime.h>
#include <math_constants.h>

#define IN_DIM   256
#define CODE_LEN 128
#define MEM_LEN  65536
#define NT       256
#define GRID_S   888          // 148 * 6
#define GRID_D   888
#define NWARP_S  (GRID_S * NT / 32)   // 7104
#define NWARP_D  (GRID_D * NT / 32)   // 7104

#define N_MD  (MEM_LEN * IN_DIM)      // 16777216 floats
#define N_MEM (MEM_LEN * CODE_LEN)    //  8388608 floats
// Aligned-slot counts: slots start at out_base+3, 4 floats each
#define S_MD  ((N_MD  - 7) / 4 + 1)   // 4194303
#define S_MEM ((N_MEM - 7) / 4 + 1)   // 2097151

// Output layout (flattened tuple, all f32):
#define OUT_MEM_OFF 1LL
#define OUT_MD_OFF  (1LL + (long long)N_MEM)
#define OUT_IDX_OFF (OUT_MD_OFF + (long long)N_MD)

// Scratch (device globals; statically armed, re-armed by the final block)
__device__ float               g_colsum[IN_DIM];                  // zero-init
__device__ float               g_colsq[IN_DIM];                   // zero-init
__device__ __align__(16) float g_enc[CODE_LEN];
__device__ int                 g_minbits = 0x7f800000;            // +inf
__device__ unsigned long long  g_argmin  = 0xFFFFFFFFFFFFFFFFULL;
__device__ unsigned            g_ticket  = 0;

// ---------------------------------------------------------------------------
// K1: mem_data [65536,256] — realigned copy (STG.128) + column sum/sumsq.
//     Warp-pair tiling: warp handles chunks [wb,wb+32) and [wb+64,wb+96);
//     thread slots k and k+64 -> SAME columns (4*64 % 256 == 0) -> one
//     accumulator set, MLP=2. Seam .w via shfl_up; lane0 scalar load.
// ---------------------------------------------------------------------------
__global__ void __launch_bounds__(NT)
k_stats(const float* __restrict__ md_f, float* __restrict__ out_md) {
    const float4* md4  = (const float4*)md_f;
    float4*       out4 = (float4*)(out_md + 3);        // 16B-aligned
    const int tid  = threadIdx.x;
    const int lane = tid & 31;
    const int wid  = tid >> 5;
    const int gw   = blockIdx.x * 8 + wid;             // global warp id
    const unsigned stride = NWARP_S * 64u;             // 454656 slots / iter

    float s0 = 0, s1 = 0, s2 = 0, s3 = 0;
    float q0 = 0, q1 = 0, q2 = 0, q3 = 0;
    unsigned wb0 = (unsigned)(gw >> 1) * 128u + (unsigned)(gw & 1) * 32u;

    for (unsigned wb = wb0; wb < S_MD; wb += stride) {
        unsigned k1 = wb + lane;
        unsigned k2 = k1 + 64u;
        bool ok1 = k1 < S_MD;
        bool ok2 = k2 < S_MD;
        float4 v1 = ok1 ? md4[k1 + 1] : make_float4(0.f, 0.f, 0.f, 0.f);
        float4 v2 = ok2 ? md4[k2 + 1] : make_float4(0.f, 0.f, 0.f, 0.f);
        float pw1 = __shfl_up_sync(0xFFFFFFFFu, v1.w, 1);
        float pw2 = __shfl_up_sync(0xFFFFFFFFu, v2.w, 1);
        if (lane == 0) {
            pw1 = md_f[4u * wb + 3u];
            if (wb + 64u < S_MD) pw2 = md_f[4u * (wb + 64u) + 3u];
        }
        if (ok1) out4[k1] = make_float4(pw1, v1.x, v1.y, v1.z);
        if (ok2) out4[k2] = make_float4(pw2, v2.x, v2.y, v2.z);
        s0 += v1.x + v2.x; q0 += v1.x * v1.x + v2.x * v2.x;
        s1 += v1.y + v2.y; q1 += v1.y * v1.y + v2.y * v2.y;
        s2 += v1.z + v2.z; q2 += v1.z * v1.z + v2.z * v2.z;
        s3 += v1.w + v2.w; q3 += v1.w * v1.w + v2.w * v2.w;
    }

    // Column of this thread's slots (constant across iterations):
    int col = (int)((4u * (wb0 + lane) + 4u) & 255u);

    __shared__ float sh_s[8][IN_DIM];
    __shared__ float sh_q[8][IN_DIM];
    // zero-init (each warp only writes 128 of its row's 256 cells)
    #pragma unroll
    for (int j = 0; j < 8; j++) { sh_s[j][tid] = 0.f; sh_q[j][tid] = 0.f; }
    __syncthreads();
    sh_s[wid][col] = s0; sh_s[wid][col + 1] = s1; sh_s[wid][col + 2] = s2; sh_s[wid][col + 3] = s3;
    sh_q[wid][col] = q0; sh_q[wid][col + 1] = q1; sh_q[wid][col + 2] = q2; sh_q[wid][col + 3] = q3;
    __syncthreads();
    float ts = 0.f, tq = 0.f;
    #pragma unroll
    for (int j = 0; j < 8; j++) { ts += sh_s[j][tid]; tq += sh_q[j][tid]; }
    atomicAdd(&g_colsum[tid], ts);
    atomicAdd(&g_colsq[tid],  tq);

    // Head (out elements 0..2) + tail (N-1) + stats for input elements 0..3
    if (blockIdx.x == 0 && tid == 0) {
        out_md[0] = md_f[0]; out_md[1] = md_f[1]; out_md[2] = md_f[2];
        out_md[N_MD - 1] = md_f[N_MD - 1];
        #pragma unroll
        for (int j = 0; j < 4; j++) {
            float v = md_f[j];
            atomicAdd(&g_colsum[j], v);
            atomicAdd(&g_colsq[j],  v * v);
        }
    }
}

// ---------------------------------------------------------------------------
// K2: enc = ((x-mean)/std) @ W.T + b — one row per block; ALSO absorbs the
//     mem_idx copy + packed argmin (2 elements per thread, overlaps with the
//     latency-bound enc work for free).
// ---------------------------------------------------------------------------
__global__ void __launch_bounds__(NT)
k_enc(const float* __restrict__ x, const float* __restrict__ W,
      const float* __restrict__ b, const int* __restrict__ idx,
      float* __restrict__ out_idx) {
    int row = blockIdx.x, t = threadIdx.x;
    int gtid = blockIdx.x * NT + t;                    // 0..32767

    // mem_idx: copy + argmin (first-index tie-break), 2 elements/thread
    unsigned long long key = 0xFFFFFFFFFFFFFFFFULL;
    #pragma unroll
    for (int h = 0; h < 2; h++) {
        int g = gtid + h * (CODE_LEN * NT);
        int v = idx[g];
        out_idx[g] = (float)v;
        unsigned long long k =
            ((unsigned long long)(unsigned)(v ^ 0x80000000) << 32) | (unsigned long long)g;
        key = (k < key) ? k : key;
    }
    #pragma unroll
    for (int off = 16; off; off >>= 1) {
        unsigned long long o = __shfl_xor_sync(0xFFFFFFFFu, key, off);
        key = (o < key) ? o : key;
    }
    if ((t & 31) == 0) atomicMin(&g_argmin, key);

    // enc row
    float mean = g_colsum[t] * (1.0f / (float)MEM_LEN);
    float var  = (g_colsq[t] - (float)MEM_LEN * mean * mean) * (1.0f / (float)(MEM_LEN - 1));
    float sd   = sqrtf(fmaxf(var, 0.0f));
    float nv   = (sd == 0.0f) ? 0.0f : (x[t] - mean) / sd;
    float p    = nv * W[row * IN_DIM + t];
    #pragma unroll
    for (int off = 16; off; off >>= 1) p += __shfl_xor_sync(0xFFFFFFFFu, p, off);
    __shared__ float red[8];
    if ((t & 31) == 0) red[t >> 5] = p;
    __syncthreads();
    if (t == 0) {
        float a = b[row];
        #pragma unroll
        for (int i = 0; i < 8; i++) a += red[i];
        g_enc[row] = a;
    }
}

// ---------------------------------------------------------------------------
// K3: memory [65536,128] — warp-per-row L1 distance + realigned copy,
//     2 rows per iteration (independent LDG.128 pair -> MLP 2).
//     Last block (ticket) writes loss + conditional scatter, re-arms globals.
// ---------------------------------------------------------------------------
__global__ void __launch_bounds__(NT)
k_dist(const float* __restrict__ mem_f, float* __restrict__ out_mem,
       const float* __restrict__ x, const int* __restrict__ count,
       float* __restrict__ out) {
    const float4* mem4 = (const float4*)mem_f;
    float4*       out4 = (float4*)(out_mem + 3);       // 16B-aligned
    const int tid   = threadIdx.x;
    const int lane  = tid & 31;
    const int warp  = (blockIdx.x * NT + tid) >> 5;

    float4 e = reinterpret_cast<const float4*>(g_enc)[lane];
    float best = CUDART_INF_F;

    for (int r = warp; r < MEM_LEN; r += 2 * NWARP_D) {
        int r2 = r + NWARP_D;
        bool ok2 = r2 < MEM_LEN;
        float4 u  = mem4[(unsigned)r * 32u + lane];
        float4 u2 = ok2 ? mem4[(unsigned)r2 * 32u + lane]
                        : make_float4(CUDART_INF_F, 0.f, 0.f, 0.f);
        // realigned copy, row r
        float ax = __shfl_down_sync(0xFFFFFFFFu, u.x, 1);
        float ay = __shfl_down_sync(0xFFFFFFFFu, u.y, 1);
        float az = __shfl_down_sync(0xFFFFFFFFu, u.z, 1);
        if (lane == 31 && r + 1 < MEM_LEN) {
            float4 t = mem4[(unsigned)(r + 1) * 32u];
            ax = t.x; ay = t.y; az = t.z;
        }
        unsigned s1 = (unsigned)r * 32u + lane;
        if (s1 < S_MEM) out4[s1] = make_float4(u.w, ax, ay, az);
        // realigned copy, row r2
        float bx = __shfl_down_sync(0xFFFFFFFFu, u2.x, 1);
        float by = __shfl_down_sync(0xFFFFFFFFu, u2.y, 1);
        float bz = __shfl_down_sync(0xFFFFFFFFu, u2.z, 1);
        if (ok2) {
            if (lane == 31 && r2 + 1 < MEM_LEN) {
                float4 t = mem4[(unsigned)(r2 + 1) * 32u];
                bx = t.x; by = t.y; bz = t.z;
            }
            unsigned s2 = (unsigned)r2 * 32u + lane;
            if (s2 < S_MEM) out4[s2] = make_float4(u2.w, bx, by, bz);
        }
        // L1 distances (u2 init -> d2 = +inf when !ok2)
        float d1 = fabsf(u.x - e.x) + fabsf(u.y - e.y) + fabsf(u.z - e.z) + fabsf(u.w - e.w);
        float d2 = ok2 ? fabsf(u2.x - e.x) + fabsf(u2.y - e.y) + fabsf(u2.z - e.z) + fabsf(u2.w - e.w)
                       : CUDART_INF_F;
        #pragma unroll
        for (int off = 16; off; off >>= 1) {
            d1 += __shfl_xor_sync(0xFFFFFFFFu, d1, off);
            d2 += __shfl_xor_sync(0xFFFFFFFFu, d2, off);
        }
        best = fminf(best, fminf(d1, d2));
    }
    if (lane == 0) atomicMin(&g_minbits, __float_as_int(best));

    if (blockIdx.x == 0 && tid == 0) {
        out_mem[0] = mem_f[0]; out_mem[1] = mem_f[1]; out_mem[2] = mem_f[2];
        out_mem[N_MEM - 1] = mem_f[N_MEM - 1];
    }

    // --- last-block final ---
    __threadfence();
    __syncthreads();
    __shared__ int s_last;
    if (tid == 0) s_last = (atomicAdd(&g_ticket, 1) == GRID_D - 1) ? 1 : 0;
    __syncthreads();
    if (s_last) {
        float loss = __int_as_float(atomicAdd(&g_minbits, 0));
        unsigned long long am = atomicAdd(&g_argmin, 0ULL);
        long long pos = (long long)(unsigned)(am & 0xFFFFFFFFULL);
        if (tid == 0) out[0] = loss;
        if (loss <= 1.0f) {
            if (tid < CODE_LEN) out[OUT_MEM_OFF + pos * CODE_LEN + tid] = g_enc[tid];
            out[OUT_MD_OFF + pos * IN_DIM + tid] = x[tid];
            if (tid == 0) out[OUT_IDX_OFF + pos] = (float)count[0];
        }
        __syncthreads();                 // done reading accumulators
        g_colsum[tid] = 0.0f;            // re-arm for next graph replay
        g_colsq[tid]  = 0.0f;
        if (tid == 0) {
            g_minbits = 0x7f800000;
            g_argmin  = 0xFFFFFFFFFFFFFFFFULL;
            g_ticket  = 0;
        }
    }
}

// ---------------------------------------------------------------------------
extern "C" void kernel_launch(void* const* d_in, const int* in_sizes, int n_in,
                              void* d_out, int out_size) {
    const float* x        = (const float*)d_in[0];
    const float* memory   = (const float*)d_in[1];
    const float* mem_data = (const float*)d_in[2];
    const int*   mem_idx  = (const int*)d_in[3];
    const float* W        = (const float*)d_in[4];
    const float* b        = (const float*)d_in[5];
    const int*   count    = (const int*)d_in[6];
    float* out = (float*)d_out;

    k_stats<<<GRID_S, NT>>>(mem_data, out + OUT_MD_OFF);
    k_enc  <<<CODE_LEN, NT>>>(x, W, b, mem_idx, out + OUT_IDX_OFF);
    k_dist <<<GRID_D, NT>>>(memory, out + OUT_MEM_OFF, x, count, out);
}

// round 8
// speedup vs baseline: 1.2263x; 1.0191x over previous
#include <cuda_runtime.h>
#include <math_constants.h>

#define IN_DIM   256
#define CODE_LEN 128
#define MEM_LEN  65536
#define NT       256
#define GRID_S   888                  // 148 * 6
#define GRID_D   1024                 // 8192 warps -> 2 quads (8 rows) per warp
#define NWARP_S  (GRID_S * NT / 32)   // 7104
#define NWARP_D  (GRID_D * NT / 32)   // 8192
#define NQUAD    (MEM_LEN / 4)        // 16384 row-quads

#define N_MD  (MEM_LEN * IN_DIM)      // 16777216 floats
#define N_MEM (MEM_LEN * CODE_LEN)    //  8388608 floats
#define S_MD  ((N_MD  - 7) / 4 + 1)   // 4194303 aligned slots
#define S_MEM ((N_MEM - 7) / 4 + 1)   // 2097151 aligned slots

// Output layout (flattened tuple, all f32):
#define OUT_MEM_OFF 1LL
#define OUT_MD_OFF  (1LL + (long long)N_MEM)
#define OUT_IDX_OFF (OUT_MD_OFF + (long long)N_MD)

// Scratch (device globals; statically armed, re-armed by the final block)
__device__ float               g_colsum[IN_DIM];                  // zero-init
__device__ float               g_colsq[IN_DIM];                   // zero-init
__device__ __align__(16) float g_enc[CODE_LEN];
__device__ int                 g_minbits = 0x7f800000;            // +inf
__device__ unsigned long long  g_argmin  = 0xFFFFFFFFFFFFFFFFULL;
__device__ unsigned            g_ticket  = 0;

#define FULL 0xFFFFFFFFu

// ---------------------------------------------------------------------------
// K1: mem_data [65536,256] — realigned copy (STG.128) + column sum/sumsq.
//     (unchanged — measured ~5.2 TB/s combined, near mixed-R/W ceiling)
// ---------------------------------------------------------------------------
__global__ void __launch_bounds__(NT)
k_stats(const float* __restrict__ md_f, float* __restrict__ out_md) {
    const float4* md4  = (const float4*)md_f;
    float4*       out4 = (float4*)(out_md + 3);        // 16B-aligned
    const int tid  = threadIdx.x;
    const int lane = tid & 31;
    const int wid  = tid >> 5;
    const int gw   = blockIdx.x * 8 + wid;
    const unsigned stride = NWARP_S * 64u;

    float s0 = 0, s1 = 0, s2 = 0, s3 = 0;
    float q0 = 0, q1 = 0, q2 = 0, q3 = 0;
    unsigned wb0 = (unsigned)(gw >> 1) * 128u + (unsigned)(gw & 1) * 32u;

    for (unsigned wb = wb0; wb < S_MD; wb += stride) {
        unsigned k1 = wb + lane;
        unsigned k2 = k1 + 64u;
        bool ok1 = k1 < S_MD;
        bool ok2 = k2 < S_MD;
        float4 v1 = ok1 ? md4[k1 + 1] : make_float4(0.f, 0.f, 0.f, 0.f);
        float4 v2 = ok2 ? md4[k2 + 1] : make_float4(0.f, 0.f, 0.f, 0.f);
        float pw1 = __shfl_up_sync(FULL, v1.w, 1);
        float pw2 = __shfl_up_sync(FULL, v2.w, 1);
        if (lane == 0) {
            pw1 = md_f[4u * wb + 3u];
            if (wb + 64u < S_MD) pw2 = md_f[4u * (wb + 64u) + 3u];
        }
        if (ok1) out4[k1] = make_float4(pw1, v1.x, v1.y, v1.z);
        if (ok2) out4[k2] = make_float4(pw2, v2.x, v2.y, v2.z);
        s0 += v1.x + v2.x; q0 += v1.x * v1.x + v2.x * v2.x;
        s1 += v1.y + v2.y; q1 += v1.y * v1.y + v2.y * v2.y;
        s2 += v1.z + v2.z; q2 += v1.z * v1.z + v2.z * v2.z;
        s3 += v1.w + v2.w; q3 += v1.w * v1.w + v2.w * v2.w;
    }

    int col = (int)((4u * (wb0 + lane) + 4u) & 255u);

    __shared__ float sh_s[8][IN_DIM];
    __shared__ float sh_q[8][IN_DIM];
    #pragma unroll
    for (int j = 0; j < 8; j++) { sh_s[j][tid] = 0.f; sh_q[j][tid] = 0.f; }
    __syncthreads();
    sh_s[wid][col] = s0; sh_s[wid][col + 1] = s1; sh_s[wid][col + 2] = s2; sh_s[wid][col + 3] = s3;
    sh_q[wid][col] = q0; sh_q[wid][col + 1] = q1; sh_q[wid][col + 2] = q2; sh_q[wid][col + 3] = q3;
    __syncthreads();
    float ts = 0.f, tq = 0.f;
    #pragma unroll
    for (int j = 0; j < 8; j++) { ts += sh_s[j][tid]; tq += sh_q[j][tid]; }
    atomicAdd(&g_colsum[tid], ts);
    atomicAdd(&g_colsq[tid],  tq);

    if (blockIdx.x == 0 && tid == 0) {
        out_md[0] = md_f[0]; out_md[1] = md_f[1]; out_md[2] = md_f[2];
        out_md[N_MD - 1] = md_f[N_MD - 1];
        #pragma unroll
        for (int j = 0; j < 4; j++) {
            float v = md_f[j];
            atomicAdd(&g_colsum[j], v);
            atomicAdd(&g_colsq[j],  v * v);
        }
    }
}

// ---------------------------------------------------------------------------
// K2: enc row per block + absorbed mem_idx copy/argmin (unchanged)
// ---------------------------------------------------------------------------
__global__ void __launch_bounds__(NT)
k_enc(const float* __restrict__ x, const float* __restrict__ W,
      const float* __restrict__ b, const int* __restrict__ idx,
      float* __restrict__ out_idx) {
    int row = blockIdx.x, t = threadIdx.x;
    int gtid = blockIdx.x * NT + t;

    unsigned long long key = 0xFFFFFFFFFFFFFFFFULL;
    #pragma unroll
    for (int h = 0; h < 2; h++) {
        int g = gtid + h * (CODE_LEN * NT);
        int v = idx[g];
        out_idx[g] = (float)v;
        unsigned long long k =
            ((unsigned long long)(unsigned)(v ^ 0x80000000) << 32) | (unsigned long long)g;
        key = (k < key) ? k : key;
    }
    #pragma unroll
    for (int off = 16; off; off >>= 1) {
        unsigned long long o = __shfl_xor_sync(FULL, key, off);
        key = (o < key) ? o : key;
    }
    if ((t & 31) == 0) atomicMin(&g_argmin, key);

    float mean = g_colsum[t] * (1.0f / (float)MEM_LEN);
    float var  = (g_colsq[t] - (float)MEM_LEN * mean * mean) * (1.0f / (float)(MEM_LEN - 1));
    float sd   = sqrtf(fmaxf(var, 0.0f));
    float nv   = (sd == 0.0f) ? 0.0f : (x[t] - mean) / sd;
    float p    = nv * W[row * IN_DIM + t];
    #pragma unroll
    for (int off = 16; off; off >>= 1) p += __shfl_xor_sync(FULL, p, off);
    __shared__ float red[8];
    if ((t & 31) == 0) red[t >> 5] = p;
    __syncthreads();
    if (t == 0) {
        float a = b[row];
        #pragma unroll
        for (int i = 0; i < 8; i++) a += red[i];
        g_enc[row] = a;
    }
}

// ---------------------------------------------------------------------------
// K3: memory [65536,128] — quad-per-warp L1 distance + realigned copy.
//     Group g=lane>>3 owns row 4q+g; lane sub=lane&7 loads 4 float4s at
//     column stride 8 (fully coalesced). Row sum = 3 shfl_xor in-group;
//     min over the quad = 2 shfl_xor across groups. Realign: store to slot
//     idx-1 with prev element's .w (shfl_up; sub==0 seam via scalar load).
// ---------------------------------------------------------------------------
__global__ void __launch_bounds__(NT)
k_dist(const float* __restrict__ mem_f, float* __restrict__ out_mem,
       const float* __restrict__ x, const int* __restrict__ count,
       float* __restrict__ out) {
    const float4* mem4 = (const float4*)mem_f;
    float4*       out4 = (float4*)(out_mem + 3);       // 16B-aligned
    const int tid  = threadIdx.x;
    const int lane = tid & 31;
    const int sub  = lane & 7;
    const int g    = lane >> 3;
    const int warp = (blockIdx.x * NT + tid) >> 5;     // 0..8191

    const float4* enc4 = (const float4*)g_enc;
    float4 e0 = enc4[sub];
    float4 e1 = enc4[sub + 8];
    float4 e2 = enc4[sub + 16];
    float4 e3 = enc4[sub + 24];

    float best = CUDART_INF_F;

    #pragma unroll
    for (int h = 0; h < 2; h++) {
        int q = warp + h * NWARP_D;                    // quad index, < 16384
        unsigned base = (unsigned)(4 * q + g) * 32u + (unsigned)sub;
        float4 v0 = mem4[base];
        float4 v1 = mem4[base + 8u];
        float4 v2 = mem4[base + 16u];
        float4 v3 = mem4[base + 24u];

        float p = fabsf(v0.x - e0.x) + fabsf(v0.y - e0.y) + fabsf(v0.z - e0.z) + fabsf(v0.w - e0.w)
                + fabsf(v1.x - e1.x) + fabsf(v1.y - e1.y) + fabsf(v1.z - e1.z) + fabsf(v1.w - e1.w)
                + fabsf(v2.x - e2.x) + fabsf(v2.y - e2.y) + fabsf(v2.z - e2.z) + fabsf(v2.w - e2.w)
                + fabsf(v3.x - e3.x) + fabsf(v3.y - e3.y) + fabsf(v3.z - e3.z) + fabsf(v3.w - e3.w);

        // realigned copy: slot i-1 = {prev elem .w, my .xyz}
        float pw0 = __shfl_up_sync(FULL, v0.w, 1);
        float pw1 = __shfl_up_sync(FULL, v1.w, 1);
        float pw2 = __shfl_up_sync(FULL, v2.w, 1);
        float pw3 = __shfl_up_sync(FULL, v3.w, 1);
        if (sub == 0) {                                 // seam within/before the row
            if (base > 0u) pw0 = mem_f[4u * base - 1u];
            pw1 = mem_f[4u * (base + 8u)  - 1u];
            pw2 = mem_f[4u * (base + 16u) - 1u];
            pw3 = mem_f[4u * (base + 24u) - 1u];
        }
        if (base != 0u) out4[base - 1u] = make_float4(pw0, v0.x, v0.y, v0.z);
        out4[base + 7u]  = make_float4(pw1, v1.x, v1.y, v1.z);
        out4[base + 15u] = make_float4(pw2, v2.x, v2.y, v2.z);
        out4[base + 23u] = make_float4(pw3, v3.x, v3.y, v3.z);

        // row sum within 8-lane group (3 steps), then min across the 4 groups
        p += __shfl_xor_sync(FULL, p, 1);
        p += __shfl_xor_sync(FULL, p, 2);
        p += __shfl_xor_sync(FULL, p, 4);
        float m = fminf(p, __shfl_xor_sync(FULL, p, 8));
        m = fminf(m, __shfl_xor_sync(FULL, m, 16));
        best = fminf(best, m);
    }
    if (lane == 0) atomicMin(&g_minbits, __float_as_int(best));

    if (blockIdx.x == 0 && tid == 0) {
        out_mem[0] = mem_f[0]; out_mem[1] = mem_f[1]; out_mem[2] = mem_f[2];
        out_mem[N_MEM - 1] = mem_f[N_MEM - 1];
    }

    // --- last-block final ---
    __threadfence();
    __syncthreads();
    __shared__ int s_last;
    if (tid == 0) s_last = (atomicAdd(&g_ticket, 1) == GRID_D - 1) ? 1 : 0;
    __syncthreads();
    if (s_last) {
        float loss = __int_as_float(atomicAdd(&g_minbits, 0));
        unsigned long long am = atomicAdd(&g_argmin, 0ULL);
        long long pos = (long long)(unsigned)(am & 0xFFFFFFFFULL);
        if (tid == 0) out[0] = loss;
        if (loss <= 1.0f) {
            if (tid < CODE_LEN) out[OUT_MEM_OFF + pos * CODE_LEN + tid] = g_enc[tid];
            out[OUT_MD_OFF + pos * IN_DIM + tid] = x[tid];
            if (tid == 0) out[OUT_IDX_OFF + pos] = (float)count[0];
        }
        __syncthreads();                 // done reading accumulators
        g_colsum[tid] = 0.0f;            // re-arm for next graph replay
        g_colsq[tid]  = 0.0f;
        if (tid == 0) {
            g_minbits = 0x7f800000;
            g_argmin  = 0xFFFFFFFFFFFFFFFFULL;
            g_ticket  = 0;
        }
    }
}

// ---------------------------------------------------------------------------
extern "C" void kernel_launch(void* const* d_in, const int* in_sizes, int n_in,
                              void* d_out, int out_size) {
    const float* x        = (const float*)d_in[0];
    const float* memory   = (const float*)d_in[1];
    const float* mem_data = (const float*)d_in[2];
    const int*   mem_idx  = (const int*)d_in[3];
    const float* W        = (const float*)d_in[4];
    const float* b        = (const float*)d_in[5];
    const int*   count    = (const int*)d_in[6];
    float* out = (float*)d_out;

    k_stats<<<GRID_S, NT>>>(mem_data, out + OUT_MD_OFF);
    k_enc  <<<CODE_LEN, NT>>>(x, W, b, mem_idx, out + OUT_IDX_OFF);
    k_dist <<<GRID_D, NT>>>(memory, out + OUT_MEM_OFF, x, count, out);
}

// round 9
// speedup vs baseline: 1.2429x; 1.0135x over previous
#include <cuda_runtime.h>
#include <math_constants.h>

#define IN_DIM   256
#define CODE_LEN 128
#define MEM_LEN  65536
#define NT       256
#define GRID_S   888                  // 148 * 6 (exactly co-resident at 6/SM)
#define GRID_D   1024                 // 8192 warps -> 2 quads (8 rows) per warp
#define NWARP_S  (GRID_S * NT / 32)   // 7104
#define NWARP_D  (GRID_D * NT / 32)   // 8192

#define N_MD  (MEM_LEN * IN_DIM)      // 16777216 floats
#define N_MEM (MEM_LEN * CODE_LEN)    //  8388608 floats
#define S_MD  ((N_MD  - 7) / 4 + 1)   // 4194303 aligned slots
#define S_MEM ((N_MEM - 7) / 4 + 1)   // 2097151 aligned slots

// Output layout (flattened tuple, all f32):
#define OUT_MEM_OFF 1LL
#define OUT_MD_OFF  (1LL + (long long)N_MEM)
#define OUT_IDX_OFF (OUT_MD_OFF + (long long)N_MD)

// Scratch (device globals; statically armed, re-armed by k_dist's final block)
__device__ float               g_colsum[IN_DIM];                  // zero-init
__device__ float               g_colsq[IN_DIM];                   // zero-init
__device__ __align__(16) float g_enc[CODE_LEN];
__device__ int                 g_minbits = 0x7f800000;            // +inf
__device__ unsigned long long  g_argmin  = 0xFFFFFFFFFFFFFFFFULL;
__device__ unsigned            g_ticket  = 0;
__device__ unsigned            g_sdone   = 0;                     // stats blocks done

#define FULL 0xFFFFFFFFu

// ---------------------------------------------------------------------------
// K1: mem_data [65536,256] — realigned copy (STG.128) + column sum/sumsq
//     (loop identical to R8) + mem_idx copy/argmin + ENC TAIL:
//     blocks 0..127 cache their W row in smem, then after all 888 blocks have
//     published their stat atomics (done-counter spin), compute enc row.
// ---------------------------------------------------------------------------
__global__ void __launch_bounds__(NT)
k_stats(const float* __restrict__ md_f, float* __restrict__ out_md,
        const int* __restrict__ idx, float* __restrict__ out_idx,
        const float* __restrict__ x, const float* __restrict__ W,
        const float* __restrict__ bias) {
    const float4* md4  = (const float4*)md_f;
    float4*       out4 = (float4*)(out_md + 3);        // 16B-aligned
    const int tid  = threadIdx.x;
    const int lane = tid & 31;
    const int wid  = tid >> 5;
    const int gw   = blockIdx.x * 8 + wid;
    const unsigned stride = NWARP_S * 64u;

    __shared__ float sW[IN_DIM];
    if (blockIdx.x < CODE_LEN) sW[tid] = W[blockIdx.x * IN_DIM + tid];

    float s0 = 0, s1 = 0, s2 = 0, s3 = 0;
    float q0 = 0, q1 = 0, q2 = 0, q3 = 0;
    unsigned wb0 = (unsigned)(gw >> 1) * 128u + (unsigned)(gw & 1) * 32u;

    for (unsigned wb = wb0; wb < S_MD; wb += stride) {
        unsigned k1 = wb + lane;
        unsigned k2 = k1 + 64u;
        bool ok1 = k1 < S_MD;
        bool ok2 = k2 < S_MD;
        float4 v1 = ok1 ? md4[k1 + 1] : make_float4(0.f, 0.f, 0.f, 0.f);
        float4 v2 = ok2 ? md4[k2 + 1] : make_float4(0.f, 0.f, 0.f, 0.f);
        float pw1 = __shfl_up_sync(FULL, v1.w, 1);
        float pw2 = __shfl_up_sync(FULL, v2.w, 1);
        if (lane == 0) {
            pw1 = md_f[4u * wb + 3u];
            if (wb + 64u < S_MD) pw2 = md_f[4u * (wb + 64u) + 3u];
        }
        if (ok1) out4[k1] = make_float4(pw1, v1.x, v1.y, v1.z);
        if (ok2) out4[k2] = make_float4(pw2, v2.x, v2.y, v2.z);
        s0 += v1.x + v2.x; q0 += v1.x * v1.x + v2.x * v2.x;
        s1 += v1.y + v2.y; q1 += v1.y * v1.y + v2.y * v2.y;
        s2 += v1.z + v2.z; q2 += v1.z * v1.z + v2.z * v2.z;
        s3 += v1.w + v2.w; q3 += v1.w * v1.w + v2.w * v2.w;
    }

    int col = (int)((4u * (wb0 + lane) + 4u) & 255u);

    __shared__ float sh_s[8][IN_DIM];
    __shared__ float sh_q[8][IN_DIM];
    #pragma unroll
    for (int j = 0; j < 8; j++) { sh_s[j][tid] = 0.f; sh_q[j][tid] = 0.f; }
    __syncthreads();
    sh_s[wid][col] = s0; sh_s[wid][col + 1] = s1; sh_s[wid][col + 2] = s2; sh_s[wid][col + 3] = s3;
    sh_q[wid][col] = q0; sh_q[wid][col + 1] = q1; sh_q[wid][col + 2] = q2; sh_q[wid][col + 3] = q3;
    __syncthreads();
    float ts = 0.f, tq = 0.f;
    #pragma unroll
    for (int j = 0; j < 8; j++) { ts += sh_s[j][tid]; tq += sh_q[j][tid]; }
    atomicAdd(&g_colsum[tid], ts);
    atomicAdd(&g_colsq[tid],  tq);

    // mem_idx copy + packed argmin (dense over blocks 0..255)
    int gtid = blockIdx.x * NT + tid;
    if (gtid < MEM_LEN) {
        int v = idx[gtid];
        out_idx[gtid] = (float)v;
        unsigned long long key =
            ((unsigned long long)(unsigned)(v ^ 0x80000000) << 32) | (unsigned long long)gtid;
        #pragma unroll
        for (int off = 16; off; off >>= 1) {
            unsigned long long o = __shfl_xor_sync(FULL, key, off);
            key = (o < key) ? o : key;
        }
        if (lane == 0) atomicMin(&g_argmin, key);
    }

    // Head/tail elements + stats for input elements 0..3
    if (blockIdx.x == 0 && tid == 0) {
        out_md[0] = md_f[0]; out_md[1] = md_f[1]; out_md[2] = md_f[2];
        out_md[N_MD - 1] = md_f[N_MD - 1];
        #pragma unroll
        for (int j = 0; j < 4; j++) {
            float v = md_f[j];
            atomicAdd(&g_colsum[j], v);
            atomicAdd(&g_colsq[j],  v * v);
        }
    }

    // Publish this block's contributions, then count it done.
    __threadfence();
    __syncthreads();
    if (tid == 0) atomicAdd(&g_sdone, 1u);

    // ---- enc tail: blocks 0..127 wait for all 888, then compute their row ----
    if (blockIdx.x < CODE_LEN) {
        if (tid == 0) {
            while (*(volatile unsigned*)&g_sdone < (unsigned)GRID_S) __nanosleep(32);
        }
        __syncthreads();
        __threadfence();   // acquire: see all g_colsum/g_colsq
        float mean = g_colsum[tid] * (1.0f / (float)MEM_LEN);
        float var  = (g_colsq[tid] - (float)MEM_LEN * mean * mean) * (1.0f / (float)(MEM_LEN - 1));
        float sd   = sqrtf(fmaxf(var, 0.0f));
        float nv   = (sd == 0.0f) ? 0.0f : (x[tid] - mean) / sd;
        float p    = nv * sW[tid];
        #pragma unroll
        for (int off = 16; off; off >>= 1) p += __shfl_xor_sync(FULL, p, off);
        __shared__ float red[8];
        if (lane == 0) red[wid] = p;
        __syncthreads();
        if (tid == 0) {
            float a = bias[blockIdx.x];
            #pragma unroll
            for (int i = 0; i < 8; i++) a += red[i];
            g_enc[blockIdx.x] = a;
        }
    }
}

// ---------------------------------------------------------------------------
// K2: memory [65536,128] — quad-per-warp L1 distance + realigned copy
//     (identical to R8) + last-block final (now also re-arms g_sdone).
// ---------------------------------------------------------------------------
__global__ void __launch_bounds__(NT)
k_dist(const float* __restrict__ mem_f, float* __restrict__ out_mem,
       const float* __restrict__ x, const int* __restrict__ count,
       float* __restrict__ out) {
    const float4* mem4 = (const float4*)mem_f;
    float4*       out4 = (float4*)(out_mem + 3);       // 16B-aligned
    const int tid  = threadIdx.x;
    const int lane = tid & 31;
    const int sub  = lane & 7;
    const int g    = lane >> 3;
    const int warp = (blockIdx.x * NT + tid) >> 5;     // 0..8191

    const float4* enc4 = (const float4*)g_enc;
    float4 e0 = enc4[sub];
    float4 e1 = enc4[sub + 8];
    float4 e2 = enc4[sub + 16];
    float4 e3 = enc4[sub + 24];

    float best = CUDART_INF_F;

    #pragma unroll
    for (int h = 0; h < 2; h++) {
        int q = warp + h * NWARP_D;                    // quad index, < 16384
        unsigned base = (unsigned)(4 * q + g) * 32u + (unsigned)sub;
        float4 v0 = mem4[base];
        float4 v1 = mem4[base + 8u];
        float4 v2 = mem4[base + 16u];
        float4 v3 = mem4[base + 24u];

        float p = fabsf(v0.x - e0.x) + fabsf(v0.y - e0.y) + fabsf(v0.z - e0.z) + fabsf(v0.w - e0.w)
                + fabsf(v1.x - e1.x) + fabsf(v1.y - e1.y) + fabsf(v1.z - e1.z) + fabsf(v1.w - e1.w)
                + fabsf(v2.x - e2.x) + fabsf(v2.y - e2.y) + fabsf(v2.z - e2.z) + fabsf(v2.w - e2.w)
                + fabsf(v3.x - e3.x) + fabsf(v3.y - e3.y) + fabsf(v3.z - e3.z) + fabsf(v3.w - e3.w);

        float pw0 = __shfl_up_sync(FULL, v0.w, 1);
        float pw1 = __shfl_up_sync(FULL, v1.w, 1);
        float pw2 = __shfl_up_sync(FULL, v2.w, 1);
        float pw3 = __shfl_up_sync(FULL, v3.w, 1);
        if (sub == 0) {
            if (base > 0u) pw0 = mem_f[4u * base - 1u];
            pw1 = mem_f[4u * (base + 8u)  - 1u];
            pw2 = mem_f[4u * (base + 16u) - 1u];
            pw3 = mem_f[4u * (base + 24u) - 1u];
        }
        if (base != 0u) out4[base - 1u] = make_float4(pw0, v0.x, v0.y, v0.z);
        out4[base + 7u]  = make_float4(pw1, v1.x, v1.y, v1.z);
        out4[base + 15u] = make_float4(pw2, v2.x, v2.y, v2.z);
        out4[base + 23u] = make_float4(pw3, v3.x, v3.y, v3.z);

        p += __shfl_xor_sync(FULL, p, 1);
        p += __shfl_xor_sync(FULL, p, 2);
        p += __shfl_xor_sync(FULL, p, 4);
        float m = fminf(p, __shfl_xor_sync(FULL, p, 8));
        m = fminf(m, __shfl_xor_sync(FULL, m, 16));
        best = fminf(best, m);
    }
    if (lane == 0) atomicMin(&g_minbits, __float_as_int(best));

    if (blockIdx.x == 0 && tid == 0) {
        out_mem[0] = mem_f[0]; out_mem[1] = mem_f[1]; out_mem[2] = mem_f[2];
        out_mem[N_MEM - 1] = mem_f[N_MEM - 1];
    }

    // --- last-block final ---
    __threadfence();
    __syncthreads();
    __shared__ int s_last;
    if (tid == 0) s_last = (atomicAdd(&g_ticket, 1) == GRID_D - 1) ? 1 : 0;
    __syncthreads();
    if (s_last) {
        float loss = __int_as_float(atomicAdd(&g_minbits, 0));
        unsigned long long am = atomicAdd(&g_argmin, 0ULL);
        long long pos = (long long)(unsigned)(am & 0xFFFFFFFFULL);
        if (tid == 0) out[0] = loss;
        if (loss <= 1.0f) {
            if (tid < CODE_LEN) out[OUT_MEM_OFF + pos * CODE_LEN + tid] = g_enc[tid];
            out[OUT_MD_OFF + pos * IN_DIM + tid] = x[tid];
            if (tid == 0) out[OUT_IDX_OFF + pos] = (float)count[0];
        }
        __syncthreads();                 // done reading accumulators
        g_colsum[tid] = 0.0f;            // re-arm for next graph replay
        g_colsq[tid]  = 0.0f;
        if (tid == 0) {
            g_minbits = 0x7f800000;
            g_argmin  = 0xFFFFFFFFFFFFFFFFULL;
            g_ticket  = 0;
            g_sdone   = 0;
        }
    }
}

// ---------------------------------------------------------------------------
extern "C" void kernel_launch(void* const* d_in, const int* in_sizes, int n_in,
                              void* d_out, int out_size) {
    const float* x        = (const float*)d_in[0];
    const float* memory   = (const float*)d_in[1];
    const float* mem_data = (const float*)d_in[2];
    const int*   mem_idx  = (const int*)d_in[3];
    const float* W        = (const float*)d_in[4];
    const float* b        = (const float*)d_in[5];
    const int*   count    = (const int*)d_in[6];
    float* out = (float*)d_out;

    k_stats<<<GRID_S, NT>>>(mem_data, out + OUT_MD_OFF,
                            mem_idx, out + OUT_IDX_OFF, x, W, b);
    k_dist <<<GRID_D, NT>>>(memory, out + OUT_MEM_OFF, x, count, out);
}